// round 7
// baseline (speedup 1.0000x reference)
#include <cuda_runtime.h>
#include <cstdint>

#define NB      2
#define H       48
#define W       48
#define HW      (H * W)          // 2304
#define DMODEL  768
#define DHEAD   64
#define NHEADS  12
#define M_TOT   (NB * HW)        // 4608
#define QKV_N   (3 * DMODEL)     // 2304

__device__ float g_qkv[(size_t)M_TOT * QKV_N];   // tf32 values: q|k|v
__device__ float g_o  [(size_t)M_TOT * DMODEL];  // tf32 values
__device__ float g_xt [(size_t)M_TOT * DMODEL];  // x, tf32
__device__ float g_wqt[(size_t)QKV_N * DMODEL];  // w_qkv, tf32
__device__ float g_wot[(size_t)DMODEL * DMODEL]; // w_out, tf32

__device__ __forceinline__ uint32_t f2tf32(float f) {
    uint32_t u;
    asm("cvt.rna.tf32.f32 %0, %1;" : "=r"(u) : "f"(f));
    return u;
}

__device__ __forceinline__ void mma_tf32(
    float& d0, float& d1, float& d2, float& d3,
    uint32_t a0, uint32_t a1, uint32_t a2, uint32_t a3,
    uint32_t b0, uint32_t b1)
{
    asm volatile(
        "mma.sync.aligned.m16n8k8.row.col.f32.tf32.tf32.f32 "
        "{%0,%1,%2,%3}, {%4,%5,%6,%7}, {%8,%9}, {%0,%1,%2,%3};"
        : "+f"(d0), "+f"(d1), "+f"(d2), "+f"(d3)
        : "r"(a0), "r"(a1), "r"(a2), "r"(a3), "r"(b0), "r"(b1));
}

__device__ __forceinline__ void cp16(uint32_t saddr, const void* g) {
    asm volatile("cp.async.cg.shared.global [%0], [%1], 16;"
                 :: "r"(saddr), "l"(g));
}
__device__ __forceinline__ uint32_t s2u(const void* p) {
    return (uint32_t)__cvta_generic_to_shared(p);
}

// ---------------------------------------------------------------------------
// Elementwise tf32 pre-convert (float4 vectorized).
// ---------------------------------------------------------------------------
__global__ void cvt_kernel(const float* __restrict__ src, float* __restrict__ dst, int n4)
{
    int i = blockIdx.x * blockDim.x + threadIdx.x;
    const int stride = gridDim.x * blockDim.x;
    for (; i < n4; i += stride) {
        float4 v = ((const float4*)src)[i];
        v.x = __uint_as_float(f2tf32(v.x));
        v.y = __uint_as_float(f2tf32(v.y));
        v.z = __uint_as_float(f2tf32(v.z));
        v.w = __uint_as_float(f2tf32(v.w));
        ((float4*)dst)[i] = v;
    }
}

// ---------------------------------------------------------------------------
// TF32 GEMM (NT), 4-stage cp.async pipeline, one __syncthreads per k-tile.
// BM=BN=128, BK=16, 256 threads, 8 warps (4x2), warp tile 32x64.
// smem [m][k], stride 20 words (conflict-free fragment banks). Dynamic smem:
// 4 stages x (A+B) = 81920 B; 2 CTAs/SM (register-limited) -> 160 KB/SM.
// ---------------------------------------------------------------------------
#define ALD 20
#define STG 4
#define STW (128 * ALD)   // words per stage per matrix

__global__ __launch_bounds__(256) void gemm_tf32_async(
    const float* __restrict__ A, const float* __restrict__ B,
    float* __restrict__ C, int M, int N, int K, int store_tf32)
{
    extern __shared__ uint32_t sm[];
    uint32_t* Asm = sm;               // [STG][128][ALD]
    uint32_t* Bsm = sm + STG * STW;   // [STG][128][ALD]

    const int tid  = threadIdx.x;
    const int lane = tid & 31;
    const int warp = tid >> 5;
    const int wm = (warp & 3) * 32;
    const int wn = (warp >> 2) * 64;
    const int rowBase = blockIdx.y * 128;
    const int colBase = blockIdx.x * 128;
    const int r = lane >> 2;   // 0..7
    const int q = lane & 3;    // 0..3

    float acc[2][8][4];
    #pragma unroll
    for (int i = 0; i < 2; i++)
        #pragma unroll
        for (int jn = 0; jn < 8; jn++)
            #pragma unroll
            for (int t = 0; t < 4; t++)
                acc[i][jn][t] = 0.0f;

    // Copy mapping: 512 16B chunks per matrix per stage, 2 per thread.
    const int L0 = tid * 2;
    const int r0 = L0 >> 2,       kc0 = (L0 & 3) * 4;
    const int r1 = (L0 + 1) >> 2, kc1 = ((L0 + 1) & 3) * 4;
    const float* Ap0 = A + (size_t)(rowBase + r0) * K + kc0;
    const float* Ap1 = A + (size_t)(rowBase + r1) * K + kc1;
    const float* Bp0 = B + (size_t)(colBase + r0) * K + kc0;
    const float* Bp1 = B + (size_t)(colBase + r1) * K + kc1;

    uint32_t sA0[STG], sA1[STG], sB0[STG], sB1[STG];
    #pragma unroll
    for (int s = 0; s < STG; s++) {
        sA0[s] = s2u(&Asm[s * STW + r0 * ALD + kc0]);
        sA1[s] = s2u(&Asm[s * STW + r1 * ALD + kc1]);
        sB0[s] = s2u(&Bsm[s * STW + r0 * ALD + kc0]);
        sB1[s] = s2u(&Bsm[s * STW + r1 * ALD + kc1]);
    }

    const int T = K / 16;   // 48 for these shapes

    // Prologue: tiles 0..STG-2 into stages 0..STG-2 (one group each)
    #pragma unroll
    for (int p = 0; p < STG - 1; p++) {
        const int k0 = p * 16;
        cp16(sA0[p], Ap0 + k0); cp16(sA1[p], Ap1 + k0);
        cp16(sB0[p], Bp0 + k0); cp16(sB1[p], Bp1 + k0);
        asm volatile("cp.async.commit_group;");
    }

    for (int t = 0; t < T; t++) {
        // Tile t complete when at most STG-2 newer groups pending.
        asm volatile("cp.async.wait_group %0;" :: "n"(STG - 2));
        __syncthreads();   // also fences: all warps done consuming stage (t-1)%STG

        // Issue tile t+STG-1 into the stage freed at iteration t-1.
        if (t + STG - 1 < T) {
            const int s  = (t + STG - 1) & (STG - 1);
            const int k0 = (t + STG - 1) * 16;
            cp16(sA0[s], Ap0 + k0); cp16(sA1[s], Ap1 + k0);
            cp16(sB0[s], Bp0 + k0); cp16(sB1[s], Bp1 + k0);
        }
        asm volatile("cp.async.commit_group;");   // empty group in tail keeps counts

        const int cur = t & (STG - 1);
        const uint32_t* Ac = Asm + cur * STW;
        const uint32_t* Bc = Bsm + cur * STW;

        #pragma unroll
        for (int kk = 0; kk < 16; kk += 8) {
            const int kA = kk + q;
            uint32_t af[2][4];
            #pragma unroll
            for (int i = 0; i < 2; i++) {
                const int rr = wm + i * 16 + r;
                af[i][0] = Ac[rr * ALD + kA];
                af[i][1] = Ac[(rr + 8) * ALD + kA];
                af[i][2] = Ac[rr * ALD + kA + 4];
                af[i][3] = Ac[(rr + 8) * ALD + kA + 4];
            }
            #pragma unroll
            for (int jn = 0; jn < 8; jn++) {
                const int cc = wn + jn * 8 + r;
                const uint32_t b0 = Bc[cc * ALD + kA];
                const uint32_t b1 = Bc[cc * ALD + kA + 4];
                #pragma unroll
                for (int i = 0; i < 2; i++)
                    mma_tf32(acc[i][jn][0], acc[i][jn][1], acc[i][jn][2], acc[i][jn][3],
                             af[i][0], af[i][1], af[i][2], af[i][3], b0, b1);
            }
        }
    }

    #pragma unroll
    for (int i = 0; i < 2; i++) {
        #pragma unroll
        for (int jn = 0; jn < 8; jn++) {
            const int row = rowBase + wm + i * 16 + r;
            const int col = colBase + wn + jn * 8 + q * 2;
            float v0 = acc[i][jn][0], v1 = acc[i][jn][1];
            float v2 = acc[i][jn][2], v3 = acc[i][jn][3];
            if (store_tf32) {
                v0 = __uint_as_float(f2tf32(v0));
                v1 = __uint_as_float(f2tf32(v1));
                v2 = __uint_as_float(f2tf32(v2));
                v3 = __uint_as_float(f2tf32(v3));
            }
            *(float2*)(C + (size_t)row * N + col)       = make_float2(v0, v1);
            *(float2*)(C + (size_t)(row + 8) * N + col) = make_float2(v2, v3);
        }
    }
}

// ---------------------------------------------------------------------------
// Tensor-core neighborhood attention (unchanged from R6 — validated).
// ---------------------------------------------------------------------------
#define QK_LD 68
#define PS_LD 50

__global__ __launch_bounds__(96) void natten_mma(const int* __restrict__ ks_ptr)
{
    __shared__ uint32_t Qs[48 * QK_LD];
    __shared__ uint32_t Ks[48 * QK_LD];
    __shared__ uint32_t Vs[48 * 64];      // swizzled
    __shared__ uint32_t Ps[48 * PS_LD];

    const int ks   = *ks_ptr;
    const int tid  = threadIdx.x;
    const int lane = tid & 31;
    const int warp = tid >> 5;
    const int qx   = blockIdx.x;
    const int head = blockIdx.y;
    const int b    = blockIdx.z;

    const int r = lane >> 2;
    const int j = lane & 3;
    const int grow = warp * 16 + r;

    const float* qbase = g_qkv + (size_t)(b * HW + qx * W) * QKV_N + head * DHEAD;
    for (int i = tid; i < 48 * 16; i += 96) {
        const int row = i >> 4, d4 = (i & 15) << 2;
        float4 v = *(const float4*)(qbase + (size_t)row * QKV_N + d4);
        uint32_t* p = &Qs[row * QK_LD + d4];
        p[0] = __float_as_uint(v.x * 0.125f);
        p[1] = __float_as_uint(v.y * 0.125f);
        p[2] = __float_as_uint(v.z * 0.125f);
        p[3] = __float_as_uint(v.w * 0.125f);
    }

    float o[8][4];
    #pragma unroll
    for (int nt = 0; nt < 8; nt++)
        #pragma unroll
        for (int t = 0; t < 4; t++)
            o[nt][t] = 0.0f;
    float m0 = -1e30f, m1 = -1e30f, l0 = 0.0f, l1 = 0.0f;

    const int x0 = max(0, qx - ks), x1 = min(H - 1, qx + ks);

    for (int kx = x0; kx <= x1; kx++) {
        __syncthreads();
        const float* krow = g_qkv + (size_t)(b * HW + kx * W) * QKV_N
                          + DMODEL + head * DHEAD;
        const float* vrow = krow + DMODEL;
        for (int i = tid; i < 48 * 16; i += 96) {
            const int key = i >> 4, d4 = (i & 15) << 2;
            const size_t off = (size_t)key * QKV_N + d4;
            uint4 kv = *(const uint4*)(krow + off);
            uint4 vv = *(const uint4*)(vrow + off);
            *(uint4*)&Ks[key * QK_LD + d4] = kv;
            *(uint4*)&Vs[key * 64 + (d4 ^ ((key & 3) << 3))] = vv;
        }
        __syncthreads();

        float sc[6][4];
        #pragma unroll
        for (int nt = 0; nt < 6; nt++)
            #pragma unroll
            for (int t = 0; t < 4; t++)
                sc[nt][t] = 0.0f;

        #pragma unroll
        for (int kk = 0; kk < 8; kk++) {
            const uint32_t a0 = Qs[(warp * 16 + r)     * QK_LD + kk * 8 + j];
            const uint32_t a1 = Qs[(warp * 16 + r + 8) * QK_LD + kk * 8 + j];
            const uint32_t a2 = Qs[(warp * 16 + r)     * QK_LD + kk * 8 + j + 4];
            const uint32_t a3 = Qs[(warp * 16 + r + 8) * QK_LD + kk * 8 + j + 4];
            #pragma unroll
            for (int nt = 0; nt < 6; nt++) {
                const uint32_t b0 = Ks[(nt * 8 + r) * QK_LD + kk * 8 + j];
                const uint32_t b1 = Ks[(nt * 8 + r) * QK_LD + kk * 8 + j + 4];
                mma_tf32(sc[nt][0], sc[nt][1], sc[nt][2], sc[nt][3],
                         a0, a1, a2, a3, b0, b1);
            }
        }

        float rmax0 = -1e30f, rmax1 = -1e30f;
        #pragma unroll
        for (int nt = 0; nt < 6; nt++) {
            const int ky0 = nt * 8 + 2 * j;
            const int ky1 = ky0 + 1;
            if (abs(grow - ky0) > ks)     sc[nt][0] = -1e30f;
            if (abs(grow - ky1) > ks)     sc[nt][1] = -1e30f;
            if (abs(grow + 8 - ky0) > ks) sc[nt][2] = -1e30f;
            if (abs(grow + 8 - ky1) > ks) sc[nt][3] = -1e30f;
            rmax0 = fmaxf(rmax0, fmaxf(sc[nt][0], sc[nt][1]));
            rmax1 = fmaxf(rmax1, fmaxf(sc[nt][2], sc[nt][3]));
        }
        rmax0 = fmaxf(rmax0, __shfl_xor_sync(0xffffffffu, rmax0, 1));
        rmax0 = fmaxf(rmax0, __shfl_xor_sync(0xffffffffu, rmax0, 2));
        rmax1 = fmaxf(rmax1, __shfl_xor_sync(0xffffffffu, rmax1, 1));
        rmax1 = fmaxf(rmax1, __shfl_xor_sync(0xffffffffu, rmax1, 2));

        const float mn0 = fmaxf(m0, rmax0);
        const float mn1 = fmaxf(m1, rmax1);
        const float cr0 = __expf(m0 - mn0);
        const float cr1 = __expf(m1 - mn1);
        m0 = mn0; m1 = mn1;

        float ps0 = 0.0f, ps1 = 0.0f;
        #pragma unroll
        for (int nt = 0; nt < 6; nt++) {
            sc[nt][0] = __expf(sc[nt][0] - mn0);
            sc[nt][1] = __expf(sc[nt][1] - mn0);
            sc[nt][2] = __expf(sc[nt][2] - mn1);
            sc[nt][3] = __expf(sc[nt][3] - mn1);
            ps0 += sc[nt][0] + sc[nt][1];
            ps1 += sc[nt][2] + sc[nt][3];
        }
        ps0 += __shfl_xor_sync(0xffffffffu, ps0, 1);
        ps0 += __shfl_xor_sync(0xffffffffu, ps0, 2);
        ps1 += __shfl_xor_sync(0xffffffffu, ps1, 1);
        ps1 += __shfl_xor_sync(0xffffffffu, ps1, 2);
        l0 = l0 * cr0 + ps0;
        l1 = l1 * cr1 + ps1;

        #pragma unroll
        for (int nt = 0; nt < 8; nt++) {
            o[nt][0] *= cr0; o[nt][1] *= cr0;
            o[nt][2] *= cr1; o[nt][3] *= cr1;
        }

        #pragma unroll
        for (int nt = 0; nt < 6; nt++) {
            uint2 p01 = make_uint2(f2tf32(sc[nt][0]), f2tf32(sc[nt][1]));
            uint2 p23 = make_uint2(f2tf32(sc[nt][2]), f2tf32(sc[nt][3]));
            *(uint2*)&Ps[(grow)     * PS_LD + nt * 8 + 2 * j] = p01;
            *(uint2*)&Ps[(grow + 8) * PS_LD + nt * 8 + 2 * j] = p23;
        }
        __syncwarp();

        #pragma unroll
        for (int kk = 0; kk < 6; kk++) {
            const uint32_t a0 = Ps[(warp * 16 + r)     * PS_LD + kk * 8 + j];
            const uint32_t a1 = Ps[(warp * 16 + r + 8) * PS_LD + kk * 8 + j];
            const uint32_t a2 = Ps[(warp * 16 + r)     * PS_LD + kk * 8 + j + 4];
            const uint32_t a3 = Ps[(warp * 16 + r + 8) * PS_LD + kk * 8 + j + 4];
            const int sw = j << 3;
            #pragma unroll
            for (int nt = 0; nt < 8; nt++) {
                const int col = (nt * 8 + r) ^ sw;
                const uint32_t b0 = Vs[(kk * 8 + j)     * 64 + col];
                const uint32_t b1 = Vs[(kk * 8 + j + 4) * 64 + col];
                mma_tf32(o[nt][0], o[nt][1], o[nt][2], o[nt][3],
                         a0, a1, a2, a3, b0, b1);
            }
        }
    }

    const float inv0 = 1.0f / l0;
    const float inv1 = 1.0f / l1;
    float* ob0 = g_o + (size_t)(b * HW + qx * W + grow)     * DMODEL + head * DHEAD;
    float* ob1 = g_o + (size_t)(b * HW + qx * W + grow + 8) * DMODEL + head * DHEAD;
    #pragma unroll
    for (int nt = 0; nt < 8; nt++) {
        const int col = nt * 8 + 2 * j;
        *(float2*)(ob0 + col) = make_float2(
            __uint_as_float(f2tf32(o[nt][0] * inv0)),
            __uint_as_float(f2tf32(o[nt][1] * inv0)));
        *(float2*)(ob1 + col) = make_float2(
            __uint_as_float(f2tf32(o[nt][2] * inv1)),
            __uint_as_float(f2tf32(o[nt][3] * inv1)));
    }
}

// ---------------------------------------------------------------------------
extern "C" void kernel_launch(void* const* d_in, const int* in_sizes, int n_in,
                              void* d_out, int out_size)
{
    const float* x      = (const float*)d_in[0];
    const float* w_qkv  = (const float*)d_in[1];
    const float* w_out  = (const float*)d_in[2];
    const int*   ksp    = (const int*)  d_in[3];
    float*       out    = (float*)d_out;

    float *qkv_ptr, *o_ptr, *xt_ptr, *wqt_ptr, *wot_ptr;
    cudaGetSymbolAddress((void**)&qkv_ptr, g_qkv);
    cudaGetSymbolAddress((void**)&o_ptr,   g_o);
    cudaGetSymbolAddress((void**)&xt_ptr,  g_xt);
    cudaGetSymbolAddress((void**)&wqt_ptr, g_wqt);
    cudaGetSymbolAddress((void**)&wot_ptr, g_wot);

    const int GEMM_SMEM = 2 * STG * STW * 4;   // 81920 B
    static int attr_set = 0;
    if (!attr_set) {
        cudaFuncSetAttribute(gemm_tf32_async,
                             cudaFuncAttributeMaxDynamicSharedMemorySize, GEMM_SMEM);
        attr_set = 1;
    }

    // 0) tf32 pre-conversion of inputs
    cvt_kernel<<<512, 256>>>(x,     xt_ptr,  M_TOT * DMODEL / 4);
    cvt_kernel<<<512, 256>>>(w_qkv, wqt_ptr, QKV_N * DMODEL / 4);
    cvt_kernel<<<256, 256>>>(w_out, wot_ptr, DMODEL * DMODEL / 4);

    // 1) QKV projection (tf32 in, tf32 out)
    {
        dim3 grid(QKV_N / 128, M_TOT / 128);
        gemm_tf32_async<<<grid, 256, GEMM_SMEM>>>(xt_ptr, wqt_ptr, qkv_ptr,
                                                  M_TOT, QKV_N, DMODEL, 1);
    }

    // 2) Tensor-core neighborhood attention
    {
        dim3 grid(H, NHEADS, NB);
        natten_mma<<<grid, 96>>>(ksp);
    }

    // 3) Output projection (tf32 in, fp32 out)
    {
        dim3 grid(DMODEL / 128, M_TOT / 128);
        gemm_tf32_async<<<grid, 256, GEMM_SMEM>>>(o_ptr, wot_ptr, out,
                                                  M_TOT, DMODEL, DMODEL, 0);
    }
}

// round 9
// speedup vs baseline: 1.4029x; 1.4029x over previous
#include <cuda_runtime.h>
#include <cuda_fp16.h>
#include <cstdint>

#define NB      2
#define H       48
#define W       48
#define HW      (H * W)          // 2304
#define DMODEL  768
#define DHEAD   64
#define NHEADS  12
#define M_TOT   (NB * HW)        // 4608
#define QKV_N   (3 * DMODEL)     // 2304

__device__ float  g_qkv[(size_t)M_TOT * QKV_N];   // tf32-valued fp32: q|k|v
__device__ __half g_o16[(size_t)M_TOT * DMODEL];  // attention output, fp16
__device__ __half g_x16[(size_t)M_TOT * DMODEL];  // x, fp16
__device__ __half g_wq16[(size_t)QKV_N * DMODEL]; // w_qkv, fp16
__device__ __half g_wo16[(size_t)DMODEL * DMODEL];// w_out, fp16

__device__ __forceinline__ uint32_t f2tf32(float f) {
    uint32_t u;
    asm("cvt.rna.tf32.f32 %0, %1;" : "=r"(u) : "f"(f));
    return u;
}

__device__ __forceinline__ uint32_t h2_bits(__half2 h) {
    return *reinterpret_cast<uint32_t*>(&h);
}

__device__ __forceinline__ void mma_tf32(
    float& d0, float& d1, float& d2, float& d3,
    uint32_t a0, uint32_t a1, uint32_t a2, uint32_t a3,
    uint32_t b0, uint32_t b1)
{
    asm volatile(
        "mma.sync.aligned.m16n8k8.row.col.f32.tf32.tf32.f32 "
        "{%0,%1,%2,%3}, {%4,%5,%6,%7}, {%8,%9}, {%0,%1,%2,%3};"
        : "+f"(d0), "+f"(d1), "+f"(d2), "+f"(d3)
        : "r"(a0), "r"(a1), "r"(a2), "r"(a3), "r"(b0), "r"(b1));
}

__device__ __forceinline__ void mma_f16(
    float& d0, float& d1, float& d2, float& d3,
    uint32_t a0, uint32_t a1, uint32_t a2, uint32_t a3,
    uint32_t b0, uint32_t b1)
{
    asm volatile(
        "mma.sync.aligned.m16n8k16.row.col.f32.f16.f16.f32 "
        "{%0,%1,%2,%3}, {%4,%5,%6,%7}, {%8,%9}, {%0,%1,%2,%3};"
        : "+f"(d0), "+f"(d1), "+f"(d2), "+f"(d3)
        : "r"(a0), "r"(a1), "r"(a2), "r"(a3), "r"(b0), "r"(b1));
}

__device__ __forceinline__ void cp16(uint32_t saddr, const void* g) {
    asm volatile("cp.async.cg.shared.global [%0], [%1], 16;"
                 :: "r"(saddr), "l"(g));
}
__device__ __forceinline__ uint32_t s2u(const void* p) {
    return (uint32_t)__cvta_generic_to_shared(p);
}

// ---------------------------------------------------------------------------
// Elementwise fp32 -> fp16 pre-convert (float4 in, 4 halves out).
// ---------------------------------------------------------------------------
__global__ void cvt16_kernel(const float* __restrict__ src,
                             __half* __restrict__ dst, int n4)
{
    int i = blockIdx.x * blockDim.x + threadIdx.x;
    const int stride = gridDim.x * blockDim.x;
    for (; i < n4; i += stride) {
        float4 v = ((const float4*)src)[i];
        uint2 o;
        o.x = h2_bits(__floats2half2_rn(v.x, v.y));
        o.y = h2_bits(__floats2half2_rn(v.z, v.w));
        ((uint2*)dst)[i] = o;
    }
}

// ---------------------------------------------------------------------------
// FP16 GEMM (NT), 2-stage cp.async pipeline: C[m][n] = sum_k A[m][k]*B[n][k]
// BM=BN=128, BK=16, 256 threads, 8 warps (4x2), warp tile 32x64.
// mma.m16n8k16.f16, fp32 accumulate.
// smem: rows of 8 half2-pairs, stride LDH=12 words (bank 12r+q: 32 distinct).
// Dynamic smem: 2 stages x 2 matrices x 128 x 12 words = 49152 B.
// store_tf32: round C to tf32 (QKV output feeds the tf32 attention MMAs).
// ---------------------------------------------------------------------------
#define LDH 12
#define SW  (128 * LDH)   // words per stage per matrix

__global__ __launch_bounds__(256) void gemm_f16_async(
    const __half* __restrict__ A, const __half* __restrict__ B,
    float* __restrict__ C, int M, int N, int K, int store_tf32)
{
    extern __shared__ uint32_t sm[];
    uint32_t* Asm = sm;             // [2][128][LDH] pairs
    uint32_t* Bsm = sm + 2 * SW;

    const int tid  = threadIdx.x;
    const int lane = tid & 31;
    const int warp = tid >> 5;
    const int wm = (warp & 3) * 32;
    const int wn = (warp >> 2) * 64;
    const int rowBase = blockIdx.y * 128;
    const int colBase = blockIdx.x * 128;
    const int r = lane >> 2;   // 0..7
    const int q = lane & 3;    // 0..3

    float acc[2][8][4];
    #pragma unroll
    for (int i = 0; i < 2; i++)
        #pragma unroll
        for (int jn = 0; jn < 8; jn++)
            #pragma unroll
            for (int t = 0; t < 4; t++)
                acc[i][jn][t] = 0.0f;

    // Copy mapping: 128 rows x 32B per matrix per stage = 256 16B chunks;
    // 256 threads -> 1 chunk per matrix. row = tid>>1, half-row = tid&1.
    const int crow = tid >> 1;
    const int chalf = tid & 1;            // 8-half granule
    const __half* Ap = A + (size_t)(rowBase + crow) * K + chalf * 8;
    const __half* Bp = B + (size_t)(colBase + crow) * K + chalf * 8;

    uint32_t sA[2], sB[2];
    #pragma unroll
    for (int s = 0; s < 2; s++) {
        sA[s] = s2u(&Asm[s * SW + crow * LDH + chalf * 4]);
        sB[s] = s2u(&Bsm[s * SW + crow * LDH + chalf * 4]);
    }

    // Prologue: tile 0 -> stage 0
    cp16(sA[0], Ap);
    cp16(sB[0], Bp);
    asm volatile("cp.async.commit_group;");

    const int T = K / 16;
    for (int t = 0; t < T; t++) {
        const int cur = t & 1;
        const int nxt = cur ^ 1;
        const bool more = (t + 1 < T);
        if (more) {
            const int k0 = (t + 1) * 16;
            cp16(sA[nxt], Ap + k0);
            cp16(sB[nxt], Bp + k0);
            asm volatile("cp.async.commit_group;");
            asm volatile("cp.async.wait_group 1;");
        } else {
            asm volatile("cp.async.wait_group 0;");
        }
        __syncthreads();

        const uint32_t* Ac = Asm + cur * SW;
        const uint32_t* Bc = Bsm + cur * SW;

        uint32_t af[2][4];
        #pragma unroll
        for (int i = 0; i < 2; i++) {
            const int rr = wm + i * 16 + r;
            af[i][0] = Ac[rr * LDH + q];
            af[i][1] = Ac[(rr + 8) * LDH + q];
            af[i][2] = Ac[rr * LDH + q + 4];
            af[i][3] = Ac[(rr + 8) * LDH + q + 4];
        }
        #pragma unroll
        for (int jn = 0; jn < 8; jn++) {
            const int cc = wn + jn * 8 + r;
            const uint32_t b0 = Bc[cc * LDH + q];
            const uint32_t b1 = Bc[cc * LDH + q + 4];
            #pragma unroll
            for (int i = 0; i < 2; i++)
                mma_f16(acc[i][jn][0], acc[i][jn][1], acc[i][jn][2], acc[i][jn][3],
                        af[i][0], af[i][1], af[i][2], af[i][3], b0, b1);
        }
        __syncthreads();   // stage cur is overwritten next iteration
    }

    #pragma unroll
    for (int i = 0; i < 2; i++) {
        #pragma unroll
        for (int jn = 0; jn < 8; jn++) {
            const int row = rowBase + wm + i * 16 + r;
            const int col = colBase + wn + jn * 8 + q * 2;
            float v0 = acc[i][jn][0], v1 = acc[i][jn][1];
            float v2 = acc[i][jn][2], v3 = acc[i][jn][3];
            if (store_tf32) {
                v0 = __uint_as_float(f2tf32(v0));
                v1 = __uint_as_float(f2tf32(v1));
                v2 = __uint_as_float(f2tf32(v2));
                v3 = __uint_as_float(f2tf32(v3));
            }
            *(float2*)(C + (size_t)row * N + col)       = make_float2(v0, v1);
            *(float2*)(C + (size_t)(row + 8) * N + col) = make_float2(v2, v3);
        }
    }
}

// ---------------------------------------------------------------------------
// Tensor-core neighborhood attention (validated R5-R7 design; writeout emits
// fp16 for the fp16 out-projection).
// ---------------------------------------------------------------------------
#define QK_LD 68
#define PS_LD 50

__global__ __launch_bounds__(96) void natten_mma(const int* __restrict__ ks_ptr)
{
    __shared__ uint32_t Qs[48 * QK_LD];
    __shared__ uint32_t Ks[48 * QK_LD];
    __shared__ uint32_t Vs[48 * 64];      // swizzled
    __shared__ uint32_t Ps[48 * PS_LD];

    const int ks   = *ks_ptr;
    const int tid  = threadIdx.x;
    const int lane = tid & 31;
    const int warp = tid >> 5;
    const int qx   = blockIdx.x;
    const int head = blockIdx.y;
    const int b    = blockIdx.z;

    const int r = lane >> 2;
    const int j = lane & 3;
    const int grow = warp * 16 + r;

    const float* qbase = g_qkv + (size_t)(b * HW + qx * W) * QKV_N + head * DHEAD;
    for (int i = tid; i < 48 * 16; i += 96) {
        const int row = i >> 4, d4 = (i & 15) << 2;
        float4 v = *(const float4*)(qbase + (size_t)row * QKV_N + d4);
        uint32_t* p = &Qs[row * QK_LD + d4];
        p[0] = __float_as_uint(v.x * 0.125f);
        p[1] = __float_as_uint(v.y * 0.125f);
        p[2] = __float_as_uint(v.z * 0.125f);
        p[3] = __float_as_uint(v.w * 0.125f);
    }

    float o[8][4];
    #pragma unroll
    for (int nt = 0; nt < 8; nt++)
        #pragma unroll
        for (int t = 0; t < 4; t++)
            o[nt][t] = 0.0f;
    float m0 = -1e30f, m1 = -1e30f, l0 = 0.0f, l1 = 0.0f;

    const int x0 = max(0, qx - ks), x1 = min(H - 1, qx + ks);

    for (int kx = x0; kx <= x1; kx++) {
        __syncthreads();
        const float* krow = g_qkv + (size_t)(b * HW + kx * W) * QKV_N
                          + DMODEL + head * DHEAD;
        const float* vrow = krow + DMODEL;
        for (int i = tid; i < 48 * 16; i += 96) {
            const int key = i >> 4, d4 = (i & 15) << 2;
            const size_t off = (size_t)key * QKV_N + d4;
            uint4 kv = *(const uint4*)(krow + off);
            uint4 vv = *(const uint4*)(vrow + off);
            *(uint4*)&Ks[key * QK_LD + d4] = kv;
            *(uint4*)&Vs[key * 64 + (d4 ^ ((key & 3) << 3))] = vv;
        }
        __syncthreads();

        float sc[6][4];
        #pragma unroll
        for (int nt = 0; nt < 6; nt++)
            #pragma unroll
            for (int t = 0; t < 4; t++)
                sc[nt][t] = 0.0f;

        #pragma unroll
        for (int kk = 0; kk < 8; kk++) {
            const uint32_t a0 = Qs[(warp * 16 + r)     * QK_LD + kk * 8 + j];
            const uint32_t a1 = Qs[(warp * 16 + r + 8) * QK_LD + kk * 8 + j];
            const uint32_t a2 = Qs[(warp * 16 + r)     * QK_LD + kk * 8 + j + 4];
            const uint32_t a3 = Qs[(warp * 16 + r + 8) * QK_LD + kk * 8 + j + 4];
            #pragma unroll
            for (int nt = 0; nt < 6; nt++) {
                const uint32_t b0 = Ks[(nt * 8 + r) * QK_LD + kk * 8 + j];
                const uint32_t b1 = Ks[(nt * 8 + r) * QK_LD + kk * 8 + j + 4];
                mma_tf32(sc[nt][0], sc[nt][1], sc[nt][2], sc[nt][3],
                         a0, a1, a2, a3, b0, b1);
            }
        }

        float rmax0 = -1e30f, rmax1 = -1e30f;
        #pragma unroll
        for (int nt = 0; nt < 6; nt++) {
            const int ky0 = nt * 8 + 2 * j;
            const int ky1 = ky0 + 1;
            if (abs(grow - ky0) > ks)     sc[nt][0] = -1e30f;
            if (abs(grow - ky1) > ks)     sc[nt][1] = -1e30f;
            if (abs(grow + 8 - ky0) > ks) sc[nt][2] = -1e30f;
            if (abs(grow + 8 - ky1) > ks) sc[nt][3] = -1e30f;
            rmax0 = fmaxf(rmax0, fmaxf(sc[nt][0], sc[nt][1]));
            rmax1 = fmaxf(rmax1, fmaxf(sc[nt][2], sc[nt][3]));
        }
        rmax0 = fmaxf(rmax0, __shfl_xor_sync(0xffffffffu, rmax0, 1));
        rmax0 = fmaxf(rmax0, __shfl_xor_sync(0xffffffffu, rmax0, 2));
        rmax1 = fmaxf(rmax1, __shfl_xor_sync(0xffffffffu, rmax1, 1));
        rmax1 = fmaxf(rmax1, __shfl_xor_sync(0xffffffffu, rmax1, 2));

        const float mn0 = fmaxf(m0, rmax0);
        const float mn1 = fmaxf(m1, rmax1);
        const float cr0 = __expf(m0 - mn0);
        const float cr1 = __expf(m1 - mn1);
        m0 = mn0; m1 = mn1;

        float ps0 = 0.0f, ps1 = 0.0f;
        #pragma unroll
        for (int nt = 0; nt < 6; nt++) {
            sc[nt][0] = __expf(sc[nt][0] - mn0);
            sc[nt][1] = __expf(sc[nt][1] - mn0);
            sc[nt][2] = __expf(sc[nt][2] - mn1);
            sc[nt][3] = __expf(sc[nt][3] - mn1);
            ps0 += sc[nt][0] + sc[nt][1];
            ps1 += sc[nt][2] + sc[nt][3];
        }
        ps0 += __shfl_xor_sync(0xffffffffu, ps0, 1);
        ps0 += __shfl_xor_sync(0xffffffffu, ps0, 2);
        ps1 += __shfl_xor_sync(0xffffffffu, ps1, 1);
        ps1 += __shfl_xor_sync(0xffffffffu, ps1, 2);
        l0 = l0 * cr0 + ps0;
        l1 = l1 * cr1 + ps1;

        #pragma unroll
        for (int nt = 0; nt < 8; nt++) {
            o[nt][0] *= cr0; o[nt][1] *= cr0;
            o[nt][2] *= cr1; o[nt][3] *= cr1;
        }

        #pragma unroll
        for (int nt = 0; nt < 6; nt++) {
            uint2 p01 = make_uint2(f2tf32(sc[nt][0]), f2tf32(sc[nt][1]));
            uint2 p23 = make_uint2(f2tf32(sc[nt][2]), f2tf32(sc[nt][3]));
            *(uint2*)&Ps[(grow)     * PS_LD + nt * 8 + 2 * j] = p01;
            *(uint2*)&Ps[(grow + 8) * PS_LD + nt * 8 + 2 * j] = p23;
        }
        __syncwarp();

        #pragma unroll
        for (int kk = 0; kk < 6; kk++) {
            const uint32_t a0 = Ps[(warp * 16 + r)     * PS_LD + kk * 8 + j];
            const uint32_t a1 = Ps[(warp * 16 + r + 8) * PS_LD + kk * 8 + j];
            const uint32_t a2 = Ps[(warp * 16 + r)     * PS_LD + kk * 8 + j + 4];
            const uint32_t a3 = Ps[(warp * 16 + r + 8) * PS_LD + kk * 8 + j + 4];
            const int sw = j << 3;
            #pragma unroll
            for (int nt = 0; nt < 8; nt++) {
                const int col = (nt * 8 + r) ^ sw;
                const uint32_t b0 = Vs[(kk * 8 + j)     * 64 + col];
                const uint32_t b1 = Vs[(kk * 8 + j + 4) * 64 + col];
                mma_tf32(o[nt][0], o[nt][1], o[nt][2], o[nt][3],
                         a0, a1, a2, a3, b0, b1);
            }
        }
    }

    // ---- writeout: fp16 (consumed by the fp16 out-projection) ----
    const float inv0 = 1.0f / l0;
    const float inv1 = 1.0f / l1;
    __half* ob0 = g_o16 + (size_t)(b * HW + qx * W + grow)     * DMODEL + head * DHEAD;
    __half* ob1 = g_o16 + (size_t)(b * HW + qx * W + grow + 8) * DMODEL + head * DHEAD;
    #pragma unroll
    for (int nt = 0; nt < 8; nt++) {
        const int col = nt * 8 + 2 * j;
        *(uint32_t*)(ob0 + col) =
            h2_bits(__floats2half2_rn(o[nt][0] * inv0, o[nt][1] * inv0));
        *(uint32_t*)(ob1 + col) =
            h2_bits(__floats2half2_rn(o[nt][2] * inv1, o[nt][3] * inv1));
    }
}

// ---------------------------------------------------------------------------
extern "C" void kernel_launch(void* const* d_in, const int* in_sizes, int n_in,
                              void* d_out, int out_size)
{
    const float* x      = (const float*)d_in[0];
    const float* w_qkv  = (const float*)d_in[1];
    const float* w_out  = (const float*)d_in[2];
    const int*   ksp    = (const int*)  d_in[3];
    float*       out    = (float*)d_out;

    float *qkv_ptr;
    __half *o16_ptr, *x16_ptr, *wq16_ptr, *wo16_ptr;
    cudaGetSymbolAddress((void**)&qkv_ptr,  g_qkv);
    cudaGetSymbolAddress((void**)&o16_ptr,  g_o16);
    cudaGetSymbolAddress((void**)&x16_ptr,  g_x16);
    cudaGetSymbolAddress((void**)&wq16_ptr, g_wq16);
    cudaGetSymbolAddress((void**)&wo16_ptr, g_wo16);

    const int GEMM_SMEM = 4 * SW * 4;   // 2 stages x 2 matrices = 49152 B
    static int attr_set = 0;
    if (!attr_set) {
        cudaFuncSetAttribute(gemm_f16_async,
                             cudaFuncAttributeMaxDynamicSharedMemorySize, GEMM_SMEM);
        attr_set = 1;
    }

    // 0) fp16 pre-conversion of inputs
    cvt16_kernel<<<512, 256>>>(x,     x16_ptr,  M_TOT * DMODEL / 4);
    cvt16_kernel<<<512, 256>>>(w_qkv, wq16_ptr, QKV_N * DMODEL / 4);
    cvt16_kernel<<<256, 256>>>(w_out, wo16_ptr, DMODEL * DMODEL / 4);

    // 1) QKV projection (fp16 in, tf32-rounded fp32 out)
    {
        dim3 grid(QKV_N / 128, M_TOT / 128);
        gemm_f16_async<<<grid, 256, GEMM_SMEM>>>(x16_ptr, wq16_ptr, qkv_ptr,
                                                 M_TOT, QKV_N, DMODEL, 1);
    }

    // 2) Tensor-core neighborhood attention (tf32 internals, fp16 writeout)
    {
        dim3 grid(H, NHEADS, NB);
        natten_mma<<<grid, 96>>>(ksp);
    }

    // 3) Output projection (fp16 in, fp32 out)
    {
        dim3 grid(DMODEL / 128, M_TOT / 128);
        gemm_f16_async<<<grid, 256, GEMM_SMEM>>>(o16_ptr, wo16_ptr, out,
                                                 M_TOT, DMODEL, DMODEL, 0);
    }
}